// round 4
// baseline (speedup 1.0000x reference)
#include <cuda_runtime.h>
#include <cuda_bf16.h>

// out[n, j] = x[n, j] + (1/512) * sum_{k=512..1023} x[n, k]
// x: [131072, 1024] f32, out: [131072, 512] f32
//
// Persistent-ish: GRID blocks of 128 threads, each block loops over rows
// row = bid, bid+GRID, bid+2*GRID, ...  Software-pipelined: the NEXT row's
// tail+head loads are issued before the CURRENT row's reduce/barrier/store,
// so DRAM requests stay in flight across the per-row sync tail.
// Double-buffered smem partials -> exactly one __syncthreads per row.

static constexpr int ROW_IN  = 1024;
static constexpr int ROW_OUT = 512;
static constexpr int THREADS = 128;
static constexpr int GRID    = 148 * 16;   // 2368 blocks, ~16/SM

__global__ __launch_bounds__(THREADS)
void projection_kernel(const float* __restrict__ x,
                       float* __restrict__ out,
                       int n_rows)
{
    int tid  = threadIdx.x;        // 0..127
    int lane = tid & 31;
    int warp = tid >> 5;

    __shared__ float partial[2][4];

    int row = blockIdx.x;
    if (row >= n_rows) return;     // GRID << n_rows, but be safe

    // prologue: loads for first row
    const float4* xr = reinterpret_cast<const float4*>(x + (size_t)row * ROW_IN);
    float4 t = __ldcs(&xr[128 + tid]);
    float4 h = __ldcs(&xr[tid]);

    int buf = 0;
    for (;;) {
        // ---- issue next row's loads BEFORE touching t/h (stay in flight
        //      through the shfl chain, barrier, and store below) ----
        int next = row + GRID;
        bool has_next = next < n_rows;
        float4 tn, hn;
        if (has_next) {
            const float4* xn = reinterpret_cast<const float4*>(x + (size_t)next * ROW_IN);
            tn = __ldcs(&xn[128 + tid]);
            hn = __ldcs(&xn[tid]);
        }

        // ---- reduce current row's tail ----
        float s = (t.x + t.y) + (t.z + t.w);
        #pragma unroll
        for (int off = 16; off > 0; off >>= 1)
            s += __shfl_xor_sync(0xFFFFFFFFu, s, off);

        if (lane == 0) partial[buf][warp] = s;
        __syncthreads();

        float total = (partial[buf][0] + partial[buf][1])
                    + (partial[buf][2] + partial[buf][3]);
        float mean = total * (1.0f / 512.0f);

        h.x += mean; h.y += mean; h.z += mean; h.w += mean;

        float4* orow = reinterpret_cast<float4*>(out + (size_t)row * ROW_OUT);
        __stcs(&orow[tid], h);

        if (!has_next) break;
        row = next;
        t = tn;
        h = hn;
        buf ^= 1;
    }
}

extern "C" void kernel_launch(void* const* d_in, const int* in_sizes, int n_in,
                              void* d_out, int out_size)
{
    const float* x = (const float*)d_in[0];
    float* out = (float*)d_out;

    int n_rows = in_sizes[0] / ROW_IN;   // 131072

    int grid = GRID < n_rows ? GRID : n_rows;
    projection_kernel<<<grid, THREADS>>>(x, out, n_rows);
}

// round 5
// speedup vs baseline: 1.0800x; 1.0800x over previous
#include <cuda_runtime.h>
#include <cuda_bf16.h>

// out[n, j] = x[n, j] + (1/512) * sum_{k=512..1023} x[n, k]
// x: [131072, 1024] f32, out: [131072, 512] f32
//
// R1 structure (best measured DRAM%): one 128-thread block per row.
//   - both float4 loads front-batched (MLP_p1=2: below L1tex contention knee)
//   - DEFAULT cache policy on loads (measured better than .cs in R3/R4)
//   - warp shfl reduce -> 4 smem partials -> one barrier -> broadcast add
//   - .cs on the store only (output is write-once, dead in cache)

static constexpr int ROW_IN  = 1024;
static constexpr int ROW_OUT = 512;
static constexpr int THREADS = 128;

__global__ __launch_bounds__(THREADS)
void projection_kernel(const float* __restrict__ x,
                       float* __restrict__ out)
{
    int tid  = threadIdx.x;
    int lane = tid & 31;
    int warp = tid >> 5;

    const float4* xrow = reinterpret_cast<const float4*>(x + (size_t)blockIdx.x * ROW_IN);
    float4*       orow = reinterpret_cast<float4*>(out + (size_t)blockIdx.x * ROW_OUT);

    // front-batch both loads (default caching — measured best)
    float4 t = xrow[128 + tid];   // tail, feeds reduction
    float4 h = xrow[tid];         // head, held for the add

    float s = (t.x + t.y) + (t.z + t.w);

    #pragma unroll
    for (int off = 16; off > 0; off >>= 1)
        s += __shfl_xor_sync(0xFFFFFFFFu, s, off);

    __shared__ float partial[4];
    if (lane == 0) partial[warp] = s;
    __syncthreads();

    float total = (partial[0] + partial[1]) + (partial[2] + partial[3]);
    float mean = total * (1.0f / 512.0f);

    h.x += mean; h.y += mean; h.z += mean; h.w += mean;

    __stcs(&orow[tid], h);
}

extern "C" void kernel_launch(void* const* d_in, const int* in_sizes, int n_in,
                              void* d_out, int out_size)
{
    const float* x = (const float*)d_in[0];
    float* out = (float*)d_out;

    int n_rows = in_sizes[0] / ROW_IN;   // 131072

    projection_kernel<<<n_rows, THREADS>>>(x, out);
}